// round 9
// baseline (speedup 1.0000x reference)
#include <cuda_runtime.h>
#include <cuda_bf16.h>
#include <cuda_fp16.h>
#include <cstdint>
#include <cstddef>

// Problem constants
#define NN     50000
#define EE     800000
#define TOT_E  (EE + NN)          // edges + self loops = 850000
#define INC    256
#define HIDC   128
#define OUTC   128
#define NEG_SLOPE 0.2f
#define GRID_M ((NN + 127) / 128) // 391

// ---------------------------------------------------------------------------
// Portable async-copy / mma helpers (sm_80+; safe for plain compute_100)
// ---------------------------------------------------------------------------
__device__ __forceinline__ uint32_t smem_u32(const void* p) {
    uint32_t a;
    asm("{ .reg .u64 t; cvta.to.shared.u64 t, %1; cvt.u32.u64 %0, t; }" : "=r"(a) : "l"(p));
    return a;
}
#define CP_ASYNC16(dst, src) \
    asm volatile("cp.async.cg.shared.global [%0], [%1], 16;" :: "r"(dst), "l"(src))
#define CP_COMMIT() asm volatile("cp.async.commit_group;" ::: "memory")
#define CP_WAIT1()  asm volatile("cp.async.wait_group 1;" ::: "memory")
#define CP_WAIT0()  asm volatile("cp.async.wait_group 0;" ::: "memory")

#define LDMATRIX_X4(r0, r1, r2, r3, addr) \
    asm volatile("ldmatrix.sync.aligned.m8n8.x4.shared.b16 {%0,%1,%2,%3}, [%4];" \
        : "=r"(r0), "=r"(r1), "=r"(r2), "=r"(r3) : "r"(addr))

#define MMA_BF16(c0, c1, c2, c3, a0, a1, a2, a3, b0, b1) \
    asm volatile("mma.sync.aligned.m16n8k16.row.col.f32.bf16.bf16.f32 " \
        "{%0,%1,%2,%3}, {%4,%5,%6,%7}, {%8,%9}, {%0,%1,%2,%3};" \
        : "+f"(c0), "+f"(c1), "+f"(c2), "+f"(c3) \
        : "r"(a0), "r"(a1), "r"(a2), "r"(a3), "r"(b0), "r"(b1))

// ---------------------------------------------------------------------------
// Scratch (device globals; no cudaMalloc allowed)
// ---------------------------------------------------------------------------
__device__ __align__(16) __half g_h1[(size_t)NN * 256];   // layer1 linear out (fp16)
__device__ __align__(16) __half g_h2[(size_t)NN * 128];   // layer2 linear out (fp16)
__device__ __align__(16) __nv_bfloat16 g_xhi[(size_t)NN * 256];
__device__ __align__(16) __nv_bfloat16 g_xlo[(size_t)NN * 256];
__device__ __align__(16) __nv_bfloat16 g_a2hi[(size_t)NN * 256];  // out1 hi
__device__ __align__(16) __nv_bfloat16 g_a2lo[(size_t)NN * 256];  // out1 lo
__device__ __align__(16) __nv_bfloat16 g_B1[256 * 512];   // W1 ext: [n][k_ext] hi|lo
__device__ __align__(16) __nv_bfloat16 g_B2[128 * 512];   // W2 ext
__device__ float g_as1[NN * 2];
__device__ float g_ad1[NN * 2];
__device__ float g_as2[NN];
__device__ float g_ad2[NN];
__device__ int   g_cnt[NN];
__device__ int   g_cur[NN];
__device__ int   g_rowptr[NN + 1];
__device__ int   g_esrc[TOT_E];

// ---------------------------------------------------------------------------
// CSR build: histogram -> scan -> scatter
// ---------------------------------------------------------------------------
__global__ void k_init_cnt() {
    int i = blockIdx.x * blockDim.x + threadIdx.x;
    if (i < NN) g_cnt[i] = 1;
}
__global__ void k_hist(const int* __restrict__ dst) {
    int i = blockIdx.x * blockDim.x + threadIdx.x;
    if (i < EE) atomicAdd(&g_cnt[dst[i]], 1);
}
__global__ void k_scan() {
    const int T = 1024;
    __shared__ int sums[T];
    int tid = threadIdx.x;
    int chunk = (NN + T - 1) / T;
    int begin = tid * chunk;
    int end   = begin + chunk; if (end > NN) end = NN;
    int s = 0;
    for (int i = begin; i < end; i++) s += g_cnt[i];
    sums[tid] = s;
    __syncthreads();
    for (int off = 1; off < T; off <<= 1) {
        int v = 0;
        if (tid >= off) v = sums[tid - off];
        __syncthreads();
        sums[tid] += v;
        __syncthreads();
    }
    int base = (tid == 0) ? 0 : sums[tid - 1];
    for (int i = begin; i < end; i++) {
        g_rowptr[i] = base;
        g_cur[i]    = base;
        base += g_cnt[i];
    }
    if (tid == T - 1) g_rowptr[NN] = base;
}
__global__ void k_scatter(const int* __restrict__ src, const int* __restrict__ dst) {
    int i = blockIdx.x * blockDim.x + threadIdx.x;
    if (i < EE) {
        int p = atomicAdd(&g_cur[dst[i]], 1);
        g_esrc[p] = src[i];
    } else if (i < TOT_E) {
        int n = i - EE;
        int p = atomicAdd(&g_cur[n], 1);
        g_esrc[p] = n;
    }
}

// ---------------------------------------------------------------------------
// Merged prep: x split (blocks 0..12499) | W1 ext (12500..12755) | W2 ext (12756..12883)
// ---------------------------------------------------------------------------
#define PREP_XB 12500   // NN*64/256
#define PREP_W1 256     // 256*256/256
#define PREP_W2 128     // 256*128/256

__global__ void k_prep_all(const float* __restrict__ x,
                           const float* __restrict__ W1,
                           const float* __restrict__ W2)
{
    int b = blockIdx.x;
    if (b < PREP_XB) {
        size_t i = (size_t)b * 256 + threadIdx.x;   // float4 index
        float4 v = ((const float4*)x)[i];
        __nv_bfloat16 h0 = __float2bfloat16(v.x), h1 = __float2bfloat16(v.y);
        __nv_bfloat16 h2 = __float2bfloat16(v.z), h3 = __float2bfloat16(v.w);
        __nv_bfloat162 a, bb, c, d;
        a.x = h0; a.y = h1; bb.x = h2; bb.y = h3;
        c.x = __float2bfloat16(v.x - __bfloat162float(h0));
        c.y = __float2bfloat16(v.y - __bfloat162float(h1));
        d.x = __float2bfloat16(v.z - __bfloat162float(h2));
        d.y = __float2bfloat16(v.w - __bfloat162float(h3));
        ((__nv_bfloat162*)g_xhi)[i * 2]     = a;
        ((__nv_bfloat162*)g_xhi)[i * 2 + 1] = bb;
        ((__nv_bfloat162*)g_xlo)[i * 2]     = c;
        ((__nv_bfloat162*)g_xlo)[i * 2 + 1] = d;
    } else if (b < PREP_XB + PREP_W1) {
        int i = (b - PREP_XB) * 256 + threadIdx.x;  // over 256*256
        int k = i >> 8, n = i & 255;
        float v = W1[i];
        __nv_bfloat16 h = __float2bfloat16(v);
        g_B1[(size_t)n * 512 + k]       = h;
        g_B1[(size_t)n * 512 + 256 + k] = __float2bfloat16(v - __bfloat162float(h));
    } else {
        int i = (b - PREP_XB - PREP_W1) * 256 + threadIdx.x;  // over 256*128
        int k = i >> 7, n = i & 127;
        float v = W2[i];
        __nv_bfloat16 h = __float2bfloat16(v);
        g_B2[(size_t)n * 512 + k]       = h;
        g_B2[(size_t)n * 512 + 256 + k] = __float2bfloat16(v - __bfloat162float(h));
    }
}

// ---------------------------------------------------------------------------
// bf16x3 mma.sync GEMM + fused alpha epilogue.
// ---------------------------------------------------------------------------
#define BK     32
#define TILE_B (128 * 64)          // 8192 bytes per tile
#define STAGE_B (4 * TILE_B)       // Ahi, Alo, Bhi, Blo
#define NSTAGE 3
#define NCHUNK 8                   // 256 / BK
#define SWZ(row, chunk) (((row) << 6) + ((((chunk) ^ (((row) >> 1) & 3))) << 4))

template <int NCOLS>
__global__ __launch_bounds__(256, 2) void k_gemm3(const __nv_bfloat16* __restrict__ Ahi,
                                                  const __nv_bfloat16* __restrict__ Alo,
                                                  const __nv_bfloat16* __restrict__ Bext,
                                                  __half* __restrict__ C, int M,
                                                  const float* __restrict__ a_s,
                                                  const float* __restrict__ a_d,
                                                  float* __restrict__ out_s,
                                                  float* __restrict__ out_d)
{
    extern __shared__ __align__(16) char smem[];
    const uint32_t sb = smem_u32(smem);
    constexpr int H = NCOLS / 128;

    const int tid  = threadIdx.x;
    const int wid  = tid >> 5;
    const int lane = tid & 31;
    const int warpM = wid & 1;      // 2 x 64 rows
    const int warpN = wid >> 1;     // 4 x 32 cols
    const int rowBlock = blockIdx.y * 128;
    const int colBlock = blockIdx.x * 128;
    const int head = (H == 2) ? blockIdx.x : 0;

    const int lrow = tid >> 1;            // 0..127
    const int c0   = (tid & 1) * 2;       // chunk16 index 0 or 2

    int gr0 = rowBlock + lrow; if (gr0 >= M) gr0 = M - 1;
    const int gn = colBlock + lrow;
    const __nv_bfloat16* aHiP = Ahi + (size_t)gr0 * 256 + c0 * 8;
    const __nv_bfloat16* aLoP = Alo + (size_t)gr0 * 256 + c0 * 8;
    const __nv_bfloat16* bHiP = Bext + (size_t)gn * 512 + c0 * 8;
    const __nv_bfloat16* bLoP = Bext + (size_t)gn * 512 + 256 + c0 * 8;
    const uint32_t w0 = SWZ(lrow, c0);
    const uint32_t w1 = SWZ(lrow, c0 + 1);

    float c[4][4][4];
#pragma unroll
    for (int i = 0; i < 4; i++)
#pragma unroll
        for (int j = 0; j < 4; j++)
#pragma unroll
            for (int q = 0; q < 4; q++) c[i][j][q] = 0.f;

    auto load_chunk = [&](int cidx) {
        const uint32_t base = sb + (cidx % NSTAGE) * STAGE_B;
        const int kin = cidx * BK;
        CP_ASYNC16(base + 0 * TILE_B + w0, aHiP + kin);
        CP_ASYNC16(base + 0 * TILE_B + w1, aHiP + kin + 8);
        CP_ASYNC16(base + 1 * TILE_B + w0, aLoP + kin);
        CP_ASYNC16(base + 1 * TILE_B + w1, aLoP + kin + 8);
        CP_ASYNC16(base + 2 * TILE_B + w0, bHiP + kin);
        CP_ASYNC16(base + 2 * TILE_B + w1, bHiP + kin + 8);
        CP_ASYNC16(base + 3 * TILE_B + w0, bLoP + kin);
        CP_ASYNC16(base + 3 * TILE_B + w1, bLoP + kin + 8);
    };

    load_chunk(0); CP_COMMIT();
    load_chunk(1); CP_COMMIT();

    for (int cidx = 0; cidx < NCHUNK; cidx++) {
        if (cidx + 1 < NCHUNK) { CP_WAIT1(); } else { CP_WAIT0(); }
        __syncthreads();
        if (cidx + 2 < NCHUNK) { load_chunk(cidx + 2); CP_COMMIT(); }

        const uint32_t stage = sb + (cidx % NSTAGE) * STAGE_B;
        const uint32_t tAhi = stage + 0 * TILE_B;
        const uint32_t tAlo = stage + 1 * TILE_B;
        const uint32_t tBhi = stage + 2 * TILE_B;
        const uint32_t tBlo = stage + 3 * TILE_B;

#pragma unroll
        for (int k16 = 0; k16 < 2; k16++) {
            const int k0 = k16 * 16;

            uint32_t bhi[8], blo[8];
#pragma unroll
            for (int np = 0; np < 2; np++) {
                const int n0 = warpN * 32 + np * 16;
                const int mat = lane >> 3;
                const int row = n0 + ((mat >> 1) << 3) + (lane & 7);
                const int col = k0 + ((mat & 1) << 3);
                const uint32_t off = SWZ(row, col >> 3);
                LDMATRIX_X4(bhi[np*4+0], bhi[np*4+1], bhi[np*4+2], bhi[np*4+3], tBhi + off);
                LDMATRIX_X4(blo[np*4+0], blo[np*4+1], blo[np*4+2], blo[np*4+3], tBlo + off);
            }
            uint32_t ahi[4][4], alo[4][4];
#pragma unroll
            for (int mt = 0; mt < 4; mt++) {
                const int m0 = warpM * 64 + mt * 16;
                const int row = m0 + (lane & 15);
                const int col = k0 + ((lane >> 4) << 3);
                const uint32_t off = SWZ(row, col >> 3);
                LDMATRIX_X4(ahi[mt][0], ahi[mt][1], ahi[mt][2], ahi[mt][3], tAhi + off);
                LDMATRIX_X4(alo[mt][0], alo[mt][1], alo[mt][2], alo[mt][3], tAlo + off);
            }
#pragma unroll
            for (int mt = 0; mt < 4; mt++) {
#pragma unroll
                for (int nt = 0; nt < 4; nt++) {
                    MMA_BF16(c[mt][nt][0], c[mt][nt][1], c[mt][nt][2], c[mt][nt][3],
                             ahi[mt][0], ahi[mt][1], ahi[mt][2], ahi[mt][3],
                             bhi[nt*2], bhi[nt*2+1]);
                    MMA_BF16(c[mt][nt][0], c[mt][nt][1], c[mt][nt][2], c[mt][nt][3],
                             alo[mt][0], alo[mt][1], alo[mt][2], alo[mt][3],
                             bhi[nt*2], bhi[nt*2+1]);
                    MMA_BF16(c[mt][nt][0], c[mt][nt][1], c[mt][nt][2], c[mt][nt][3],
                             ahi[mt][0], ahi[mt][1], ahi[mt][2], ahi[mt][3],
                             blo[nt*2], blo[nt*2+1]);
                }
            }
        }
    }

    // ---- fused alpha partials (fp32 h) ----
    float ps[4][2] = {{0.f,0.f},{0.f,0.f},{0.f,0.f},{0.f,0.f}};
    float pd[4][2] = {{0.f,0.f},{0.f,0.f},{0.f,0.f},{0.f,0.f}};
    {
        const float* avs = a_s + head * 128;
        const float* avd = a_d + head * 128;
#pragma unroll
        for (int nt = 0; nt < 4; nt++) {
            int lc = warpN * 32 + nt * 8 + 2 * (lane & 3);
            float s0 = avs[lc], s1 = avs[lc + 1];
            float d0 = avd[lc], d1 = avd[lc + 1];
#pragma unroll
            for (int mt = 0; mt < 4; mt++) {
                ps[mt][0] += c[mt][nt][0] * s0 + c[mt][nt][1] * s1;
                ps[mt][1] += c[mt][nt][2] * s0 + c[mt][nt][3] * s1;
                pd[mt][0] += c[mt][nt][0] * d0 + c[mt][nt][1] * d1;
                pd[mt][1] += c[mt][nt][2] * d0 + c[mt][nt][3] * d1;
            }
        }
#pragma unroll
        for (int mt = 0; mt < 4; mt++)
#pragma unroll
            for (int r = 0; r < 2; r++) {
                ps[mt][r] += __shfl_xor_sync(0xFFFFFFFFu, ps[mt][r], 1);
                ps[mt][r] += __shfl_xor_sync(0xFFFFFFFFu, ps[mt][r], 2);
                pd[mt][r] += __shfl_xor_sync(0xFFFFFFFFu, pd[mt][r], 1);
                pd[mt][r] += __shfl_xor_sync(0xFFFFFFFFu, pd[mt][r], 2);
            }
    }
    __syncthreads();                       // stage smem no longer needed
    float* sred = (float*)smem;            // [2][128][4]
    if ((lane & 3) == 0) {
#pragma unroll
        for (int mt = 0; mt < 4; mt++) {
            int r0 = warpM * 64 + mt * 16 + (lane >> 2);
            sred[(r0)     * 4 + warpN] = ps[mt][0];
            sred[(r0 + 8) * 4 + warpN] = ps[mt][1];
            sred[(128 + r0)     * 4 + warpN] = pd[mt][0];
            sred[(128 + r0 + 8) * 4 + warpN] = pd[mt][1];
        }
    }

    // C stores (global, overlap with smem writes)
#pragma unroll
    for (int mt = 0; mt < 4; mt++) {
        int r0 = rowBlock + warpM * 64 + mt * 16 + (lane >> 2);
#pragma unroll
        for (int nt = 0; nt < 4; nt++) {
            int cg = colBlock + warpN * 32 + nt * 8 + 2 * (lane & 3);
            if (r0 < M)
                *(__half2*)(C + (size_t)r0 * NCOLS + cg) =
                    __floats2half2_rn(c[mt][nt][0], c[mt][nt][1]);
            if (r0 + 8 < M)
                *(__half2*)(C + (size_t)(r0 + 8) * NCOLS + cg) =
                    __floats2half2_rn(c[mt][nt][2], c[mt][nt][3]);
        }
    }
    __syncthreads();
    if (tid < 128) {
        int gr = rowBlock + tid;
        if (gr < M) {
            float ssum = sred[tid * 4] + sred[tid * 4 + 1] + sred[tid * 4 + 2] + sred[tid * 4 + 3];
            float dsum = sred[(128 + tid) * 4] + sred[(128 + tid) * 4 + 1] +
                         sred[(128 + tid) * 4 + 2] + sred[(128 + tid) * 4 + 3];
            out_s[gr * H + head] = ssum;
            out_d[gr * H + head] = dsum;
        }
    }
}

// ---------------------------------------------------------------------------
// Aggregation (no max pass — softmax shift-invariant, scores O(1))
// ---------------------------------------------------------------------------
__device__ __forceinline__ float warp_sum(float v) {
#pragma unroll
    for (int o = 16; o; o >>= 1) v += __shfl_xor_sync(0xFFFFFFFFu, v, o);
    return v;
}
__device__ __forceinline__ float lrelu(float x) { return x > 0.f ? x : NEG_SLOPE * x; }
__device__ __forceinline__ float eluf(float x)  { return x > 0.f ? x : (__expf(x) - 1.f); }

__device__ __forceinline__ void store4_hilo(__nv_bfloat16* hi, __nv_bfloat16* lo,
                                            size_t off, float4 v) {
    __nv_bfloat16 h0 = __float2bfloat16(v.x), h1 = __float2bfloat16(v.y);
    __nv_bfloat16 h2 = __float2bfloat16(v.z), h3 = __float2bfloat16(v.w);
    __nv_bfloat16 l0 = __float2bfloat16(v.x - __bfloat162float(h0));
    __nv_bfloat16 l1 = __float2bfloat16(v.y - __bfloat162float(h1));
    __nv_bfloat16 l2 = __float2bfloat16(v.z - __bfloat162float(h2));
    __nv_bfloat16 l3 = __float2bfloat16(v.w - __bfloat162float(h3));
    __nv_bfloat162 a, b, cc, d;
    a.x = h0; a.y = h1; b.x = h2; b.y = h3;
    cc.x = l0; cc.y = l1; d.x = l2; d.y = l3;
    *(__nv_bfloat162*)(hi + off)     = a;
    *(__nv_bfloat162*)(hi + off + 2) = b;
    *(__nv_bfloat162*)(lo + off)     = cc;
    *(__nv_bfloat162*)(lo + off + 2) = d;
}

// Layer 1: H=2, C=128/head. out1 = elu(agg + b1), stored as bf16 hi/lo for GEMM2.
__global__ __launch_bounds__(256) void k_agg1(const float* __restrict__ b1)
{
    int w = (blockIdx.x * blockDim.x + threadIdx.x) >> 5;
    int lane = threadIdx.x & 31;
    if (w >= NN) return;
    int node = w;
    int beg = g_rowptr[node], end = g_rowptr[node + 1];
    float ad0 = g_ad1[2 * node], ad1v = g_ad1[2 * node + 1];

    float4 acc0 = make_float4(0.f, 0.f, 0.f, 0.f);
    float4 acc1 = make_float4(0.f, 0.f, 0.f, 0.f);
    float d0 = 0.f, d1 = 0.f;
    const uint2* hbase = (const uint2*)g_h1;   // row = 64 uint2 (256 fp16)

    for (int t = beg; t < end; t += 32) {
        int n = end - t; if (n > 32) n = 32;
        int idx = 0; float w0 = 0.f, w1 = 0.f;
        if (lane < n) {
            idx = g_esrc[t + lane];
            float2 as = *(const float2*)&g_as1[2 * idx];
            w0 = __expf(lrelu(as.x + ad0));
            w1 = __expf(lrelu(as.y + ad1v));
        }
        d0 += w0; d1 += w1;
#pragma unroll 4
        for (int j = 0; j < n; j++) {
            int s    = __shfl_sync(0xFFFFFFFFu, idx, j);
            float u0 = __shfl_sync(0xFFFFFFFFu, w0, j);
            float u1 = __shfl_sync(0xFFFFFFFFu, w1, j);
            uint2 ua = hbase[(size_t)s * 64 + lane];
            uint2 ub = hbase[(size_t)s * 64 + 32 + lane];
            float2 a01 = __half22float2(*(__half2*)&ua.x);
            float2 a23 = __half22float2(*(__half2*)&ua.y);
            float2 b01 = __half22float2(*(__half2*)&ub.x);
            float2 b23 = __half22float2(*(__half2*)&ub.y);
            acc0.x += u0 * a01.x; acc0.y += u0 * a01.y; acc0.z += u0 * a23.x; acc0.w += u0 * a23.y;
            acc1.x += u1 * b01.x; acc1.y += u1 * b01.y; acc1.z += u1 * b23.x; acc1.w += u1 * b23.y;
        }
    }
    d0 = warp_sum(d0); d1 = warp_sum(d1);
    float inv0 = 1.f / d0, inv1 = 1.f / d1;
    float4 bb0 = ((const float4*)b1)[lane];
    float4 bb1 = ((const float4*)b1)[32 + lane];
    float4 o0, o1;
    o0.x = eluf(acc0.x * inv0 + bb0.x);
    o0.y = eluf(acc0.y * inv0 + bb0.y);
    o0.z = eluf(acc0.z * inv0 + bb0.z);
    o0.w = eluf(acc0.w * inv0 + bb0.w);
    o1.x = eluf(acc1.x * inv1 + bb1.x);
    o1.y = eluf(acc1.y * inv1 + bb1.y);
    o1.z = eluf(acc1.z * inv1 + bb1.z);
    o1.w = eluf(acc1.w * inv1 + bb1.w);
    store4_hilo(g_a2hi, g_a2lo, (size_t)node * 256 + lane * 4, o0);
    store4_hilo(g_a2hi, g_a2lo, (size_t)node * 256 + 128 + lane * 4, o1);
}

// Layer 2: H=1, C=128. out = agg + b2 -> d_out (fp32).
__global__ __launch_bounds__(256) void k_agg2(const float* __restrict__ b2,
                                              float* __restrict__ out)
{
    int w = (blockIdx.x * blockDim.x + threadIdx.x) >> 5;
    int lane = threadIdx.x & 31;
    if (w >= NN) return;
    int node = w;
    int beg = g_rowptr[node], end = g_rowptr[node + 1];
    float ad = g_ad2[node];

    float4 acc = make_float4(0.f, 0.f, 0.f, 0.f);
    float d = 0.f;
    const uint2* hbase = (const uint2*)g_h2;   // row = 32 uint2 (128 fp16)

    for (int t = beg; t < end; t += 32) {
        int n = end - t; if (n > 32) n = 32;
        int idx = 0; float wv = 0.f;
        if (lane < n) {
            idx = g_esrc[t + lane];
            wv = __expf(lrelu(g_as2[idx] + ad));
        }
        d += wv;
#pragma unroll 4
        for (int j = 0; j < n; j++) {
            int s   = __shfl_sync(0xFFFFFFFFu, idx, j);
            float u = __shfl_sync(0xFFFFFFFFu, wv, j);
            uint2 uv = hbase[(size_t)s * 32 + lane];
            float2 v01 = __half22float2(*(__half2*)&uv.x);
            float2 v23 = __half22float2(*(__half2*)&uv.y);
            acc.x += u * v01.x; acc.y += u * v01.y; acc.z += u * v23.x; acc.w += u * v23.y;
        }
    }
    d = warp_sum(d);
    float inv = 1.f / d;
    float4 bb = ((const float4*)b2)[lane];
    float4 o;
    o.x = acc.x * inv + bb.x;
    o.y = acc.y * inv + bb.y;
    o.z = acc.z * inv + bb.z;
    o.w = acc.w * inv + bb.w;
    ((float4*)out)[(size_t)node * 32 + lane] = o;
}

// ---------------------------------------------------------------------------
// Launch. Stream fork is used ONLY if stream/event creation verifiably
// succeeded; otherwise a fully serial single-stream order (proven R6-style
// topology) is used. Both orders satisfy all data dependencies.
// ---------------------------------------------------------------------------
extern "C" void kernel_launch(void* const* d_in, const int* in_sizes, int n_in,
                              void* d_out, int out_size)
{
    const float* x      = (const float*)d_in[0];
    const int*   eidx   = (const int*)d_in[1];
    const float* W1     = (const float*)d_in[2];
    const float* a_src1 = (const float*)d_in[3];
    const float* a_dst1 = (const float*)d_in[4];
    const float* b1     = (const float*)d_in[5];
    const float* W2     = (const float*)d_in[6];
    const float* a_src2 = (const float*)d_in[7];
    const float* a_dst2 = (const float*)d_in[8];
    const float* b2     = (const float*)d_in[9];
    float* out = (float*)d_out;

    const int* e_src = eidx;
    const int* e_dst = eidx + EE;

    __half* p_h1 = nullptr; cudaGetSymbolAddress((void**)&p_h1, g_h1);
    __half* p_h2 = nullptr; cudaGetSymbolAddress((void**)&p_h2, g_h2);
    float* p_as1 = nullptr; cudaGetSymbolAddress((void**)&p_as1, g_as1);
    float* p_ad1 = nullptr; cudaGetSymbolAddress((void**)&p_ad1, g_ad1);
    float* p_as2 = nullptr; cudaGetSymbolAddress((void**)&p_as2, g_as2);
    float* p_ad2 = nullptr; cudaGetSymbolAddress((void**)&p_ad2, g_ad2);
    __nv_bfloat16 *p_xhi, *p_xlo, *p_a2hi, *p_a2lo, *p_B1, *p_B2;
    cudaGetSymbolAddress((void**)&p_xhi,  g_xhi);
    cudaGetSymbolAddress((void**)&p_xlo,  g_xlo);
    cudaGetSymbolAddress((void**)&p_a2hi, g_a2hi);
    cudaGetSymbolAddress((void**)&p_a2lo, g_a2lo);
    cudaGetSymbolAddress((void**)&p_B1,   g_B1);
    cudaGetSymbolAddress((void**)&p_B2,   g_B2);

    constexpr int GSMEM = NSTAGE * STAGE_B;   // 98304 bytes
    static bool init_done = false;
    static bool use_fork = false;
    static cudaStream_t s2 = nullptr;
    static cudaEvent_t evFork = nullptr, evJoin = nullptr;
    if (!init_done) {
        init_done = true;
        cudaFuncSetAttribute(k_gemm3<256>, cudaFuncAttributeMaxDynamicSharedMemorySize, GSMEM);
        cudaFuncSetAttribute(k_gemm3<128>, cudaFuncAttributeMaxDynamicSharedMemorySize, GSMEM);
        bool ok = (cudaStreamCreateWithFlags(&s2, cudaStreamNonBlocking) == cudaSuccess);
        ok = ok && (cudaEventCreateWithFlags(&evFork, cudaEventDisableTiming) == cudaSuccess);
        ok = ok && (cudaEventCreateWithFlags(&evJoin, cudaEventDisableTiming) == cudaSuccess);
        use_fork = ok && (s2 != nullptr) && (evFork != nullptr) && (evJoin != nullptr);
    }

    if (use_fork) {
        // launch 1: merged prep (main stream)
        k_prep_all<<<PREP_XB + PREP_W1 + PREP_W2, 256>>>(x, W1, W2);

        // fork CSR onto s2
        cudaEventRecord(evFork, 0);
        cudaStreamWaitEvent(s2, evFork, 0);
        k_init_cnt<<<(NN + 255) / 256, 256, 0, s2>>>();
        k_hist<<<(EE + 255) / 256, 256, 0, s2>>>(e_dst);

        // launch 4 (profiled): GEMM1 + fused alpha
        {
            dim3 grid(2, GRID_M);
            k_gemm3<256><<<grid, 256, GSMEM>>>(p_xhi, p_xlo, p_B1, p_h1, NN,
                                               a_src1, a_dst1, p_as1, p_ad1);
        }

        k_scan<<<1, 1024, 0, s2>>>();
        k_scatter<<<(TOT_E + 255) / 256, 256, 0, s2>>>(e_src, e_dst);
        cudaEventRecord(evJoin, s2);
        cudaStreamWaitEvent(0, evJoin, 0);

        k_agg1<<<(NN * 32 + 255) / 256, 256>>>(b1);
        {
            dim3 grid(1, GRID_M);
            k_gemm3<128><<<grid, 256, GSMEM>>>(p_a2hi, p_a2lo, p_B2, p_h2, NN,
                                               a_src2, a_dst2, p_as2, p_ad2);
        }
        k_agg2<<<(NN * 32 + 255) / 256, 256>>>(b2, out);
    } else {
        // Serial fallback: single stream, all deps in order.
        k_prep_all<<<PREP_XB + PREP_W1 + PREP_W2, 256>>>(x, W1, W2);
        k_init_cnt<<<(NN + 255) / 256, 256>>>();
        k_hist<<<(EE + 255) / 256, 256>>>(e_dst);
        {
            dim3 grid(2, GRID_M);
            k_gemm3<256><<<grid, 256, GSMEM>>>(p_xhi, p_xlo, p_B1, p_h1, NN,
                                               a_src1, a_dst1, p_as1, p_ad1);
        }
        k_scan<<<1, 1024>>>();
        k_scatter<<<(TOT_E + 255) / 256, 256>>>(e_src, e_dst);
        k_agg1<<<(NN * 32 + 255) / 256, 256>>>(b1);
        {
            dim3 grid(1, GRID_M);
            k_gemm3<128><<<grid, 256, GSMEM>>>(p_a2hi, p_a2lo, p_B2, p_h2, NN,
                                               a_src2, a_dst2, p_as2, p_ad2);
        }
        k_agg2<<<(NN * 32 + 255) / 256, 256>>>(b2, out);
    }
}

// round 10
// speedup vs baseline: 1.4312x; 1.4312x over previous
#include <cuda_runtime.h>
#include <cuda_bf16.h>
#include <cuda_fp16.h>
#include <cstdint>
#include <cstddef>

// Problem constants
#define NN     50000
#define EE     800000
#define TOT_E  (EE + NN)          // edges + self loops = 850000
#define NEG_SLOPE 0.2f
#define GRID_M ((NN + 127) / 128) // 391
#define SCAN_B ((NN + 255) / 256) // 196

// ---------------------------------------------------------------------------
// Portable async-copy / mma helpers (sm_80+; safe for plain compute_100)
// ---------------------------------------------------------------------------
__device__ __forceinline__ uint32_t smem_u32(const void* p) {
    uint32_t a;
    asm("{ .reg .u64 t; cvta.to.shared.u64 t, %1; cvt.u32.u64 %0, t; }" : "=r"(a) : "l"(p));
    return a;
}
#define CP_ASYNC16(dst, src) \
    asm volatile("cp.async.cg.shared.global [%0], [%1], 16;" :: "r"(dst), "l"(src))
#define CP_COMMIT() asm volatile("cp.async.commit_group;" ::: "memory")
#define CP_WAIT1()  asm volatile("cp.async.wait_group 1;" ::: "memory")
#define CP_WAIT0()  asm volatile("cp.async.wait_group 0;" ::: "memory")

#define LDMATRIX_X4(r0, r1, r2, r3, addr) \
    asm volatile("ldmatrix.sync.aligned.m8n8.x4.shared.b16 {%0,%1,%2,%3}, [%4];" \
        : "=r"(r0), "=r"(r1), "=r"(r2), "=r"(r3) : "r"(addr))

#define MMA_BF16(c0, c1, c2, c3, a0, a1, a2, a3, b0, b1) \
    asm volatile("mma.sync.aligned.m16n8k16.row.col.f32.bf16.bf16.f32 " \
        "{%0,%1,%2,%3}, {%4,%5,%6,%7}, {%8,%9}, {%0,%1,%2,%3};" \
        : "+f"(c0), "+f"(c1), "+f"(c2), "+f"(c3) \
        : "r"(a0), "r"(a1), "r"(a2), "r"(a3), "r"(b0), "r"(b1))

// ---------------------------------------------------------------------------
// Scratch (device globals; no cudaMalloc allowed)
// ---------------------------------------------------------------------------
__device__ __align__(16) __half g_h1[(size_t)NN * 256];   // layer1 linear out (fp16)
__device__ __align__(16) __half g_h2[(size_t)NN * 128];   // layer2 linear out (fp16)
__device__ __align__(16) __nv_bfloat16 g_xhi[(size_t)NN * 256];
__device__ __align__(16) __nv_bfloat16 g_xlo[(size_t)NN * 256];
__device__ __align__(16) __nv_bfloat16 g_a2hi[(size_t)NN * 256];  // out1 hi
__device__ __align__(16) __nv_bfloat16 g_a2lo[(size_t)NN * 256];  // out1 lo
__device__ __align__(16) __nv_bfloat16 g_B1[256 * 512];   // W1 ext: [n][k_ext] hi|lo
__device__ __align__(16) __nv_bfloat16 g_B2[128 * 512];   // W2 ext
__device__ float g_as1[NN * 2];
__device__ float g_ad1[NN * 2];
__device__ float g_as2[NN];
__device__ float g_ad2[NN];
__device__ int   g_cnt[NN];
__device__ int   g_cur[NN];
__device__ int   g_rowptr[NN + 1];
__device__ int   g_esrc[TOT_E];
__device__ int   g_bsum[256];
__device__ int   g_boff[256];

// ---------------------------------------------------------------------------
// CSR build: histogram -> hierarchical coalesced scan -> scatter
// ---------------------------------------------------------------------------
__global__ void k_init_cnt() {
    int i = blockIdx.x * blockDim.x + threadIdx.x;
    if (i < NN) g_cnt[i] = 1;
}
__global__ void k_hist(const int* __restrict__ dst) {
    int i = blockIdx.x * blockDim.x + threadIdx.x;
    if (i < EE) atomicAdd(&g_cnt[dst[i]], 1);
}
// scan1: per-block sum of 256 counts (coalesced)
__global__ void k_scan1() {
    __shared__ int sm[256];
    int i = blockIdx.x * 256 + threadIdx.x;
    sm[threadIdx.x] = (i < NN) ? g_cnt[i] : 0;
    __syncthreads();
    for (int off = 128; off; off >>= 1) {
        if (threadIdx.x < off) sm[threadIdx.x] += sm[threadIdx.x + off];
        __syncthreads();
    }
    if (threadIdx.x == 0) g_bsum[blockIdx.x] = sm[0];
}
// scan2: single block scans the 196 block sums -> exclusive offsets
__global__ void k_scan2() {
    __shared__ int sm[256];
    int t = threadIdx.x;
    int v = (t < SCAN_B) ? g_bsum[t] : 0;
    sm[t] = v;
    __syncthreads();
    for (int off = 1; off < 256; off <<= 1) {
        int u = (t >= off) ? sm[t - off] : 0;
        __syncthreads();
        sm[t] += u;
        __syncthreads();
    }
    g_boff[t] = sm[t] - v;   // exclusive
}
// scan3: block-level inclusive scan + block offset -> rowptr/cur (coalesced)
__global__ void k_scan3() {
    __shared__ int sm[256];
    int t = threadIdx.x;
    int i = blockIdx.x * 256 + t;
    int v = (i < NN) ? g_cnt[i] : 0;
    sm[t] = v;
    __syncthreads();
    for (int off = 1; off < 256; off <<= 1) {
        int u = (t >= off) ? sm[t - off] : 0;
        __syncthreads();
        sm[t] += u;
        __syncthreads();
    }
    if (i < NN) {
        int excl = sm[t] - v + g_boff[blockIdx.x];
        g_rowptr[i] = excl;
        g_cur[i]    = excl;
        if (i == NN - 1) g_rowptr[NN] = excl + v;
    }
}
__global__ void k_scatter(const int* __restrict__ src, const int* __restrict__ dst) {
    int i = blockIdx.x * blockDim.x + threadIdx.x;
    if (i < EE) {
        int p = atomicAdd(&g_cur[dst[i]], 1);
        g_esrc[p] = src[i];
    } else if (i < TOT_E) {
        int n = i - EE;
        int p = atomicAdd(&g_cur[n], 1);
        g_esrc[p] = n;
    }
}

// ---------------------------------------------------------------------------
// Merged prep: x split (blocks 0..12499) | W1 ext | W2 ext
// ---------------------------------------------------------------------------
#define PREP_XB 12500   // NN*64/256
#define PREP_W1 256     // 256*256/256
#define PREP_W2 128     // 256*128/256

__global__ void k_prep_all(const float* __restrict__ x,
                           const float* __restrict__ W1,
                           const float* __restrict__ W2)
{
    int b = blockIdx.x;
    if (b < PREP_XB) {
        size_t i = (size_t)b * 256 + threadIdx.x;   // float4 index
        float4 v = ((const float4*)x)[i];
        __nv_bfloat16 h0 = __float2bfloat16(v.x), h1 = __float2bfloat16(v.y);
        __nv_bfloat16 h2 = __float2bfloat16(v.z), h3 = __float2bfloat16(v.w);
        __nv_bfloat162 a, bb, c, d;
        a.x = h0; a.y = h1; bb.x = h2; bb.y = h3;
        c.x = __float2bfloat16(v.x - __bfloat162float(h0));
        c.y = __float2bfloat16(v.y - __bfloat162float(h1));
        d.x = __float2bfloat16(v.z - __bfloat162float(h2));
        d.y = __float2bfloat16(v.w - __bfloat162float(h3));
        ((__nv_bfloat162*)g_xhi)[i * 2]     = a;
        ((__nv_bfloat162*)g_xhi)[i * 2 + 1] = bb;
        ((__nv_bfloat162*)g_xlo)[i * 2]     = c;
        ((__nv_bfloat162*)g_xlo)[i * 2 + 1] = d;
    } else if (b < PREP_XB + PREP_W1) {
        int i = (b - PREP_XB) * 256 + threadIdx.x;  // over 256*256
        int k = i >> 8, n = i & 255;
        float v = W1[i];
        __nv_bfloat16 h = __float2bfloat16(v);
        g_B1[(size_t)n * 512 + k]       = h;
        g_B1[(size_t)n * 512 + 256 + k] = __float2bfloat16(v - __bfloat162float(h));
    } else {
        int i = (b - PREP_XB - PREP_W1) * 256 + threadIdx.x;  // over 256*128
        int k = i >> 7, n = i & 127;
        float v = W2[i];
        __nv_bfloat16 h = __float2bfloat16(v);
        g_B2[(size_t)n * 512 + k]       = h;
        g_B2[(size_t)n * 512 + 256 + k] = __float2bfloat16(v - __bfloat162float(h));
    }
}

// ---------------------------------------------------------------------------
// bf16x3 mma.sync GEMM + fused alpha epilogue.
// ---------------------------------------------------------------------------
#define BK     32
#define TILE_B (128 * 64)          // 8192 bytes per tile
#define STAGE_B (4 * TILE_B)       // Ahi, Alo, Bhi, Blo
#define NSTAGE 3
#define NCHUNK 8                   // 256 / BK
#define SWZ(row, chunk) (((row) << 6) + ((((chunk) ^ (((row) >> 1) & 3))) << 4))

template <int NCOLS>
__global__ __launch_bounds__(256, 2) void k_gemm3(const __nv_bfloat16* __restrict__ Ahi,
                                                  const __nv_bfloat16* __restrict__ Alo,
                                                  const __nv_bfloat16* __restrict__ Bext,
                                                  __half* __restrict__ C, int M,
                                                  const float* __restrict__ a_s,
                                                  const float* __restrict__ a_d,
                                                  float* __restrict__ out_s,
                                                  float* __restrict__ out_d)
{
    extern __shared__ __align__(16) char smem[];
    const uint32_t sb = smem_u32(smem);
    constexpr int H = NCOLS / 128;

    const int tid  = threadIdx.x;
    const int wid  = tid >> 5;
    const int lane = tid & 31;
    const int warpM = wid & 1;      // 2 x 64 rows
    const int warpN = wid >> 1;     // 4 x 32 cols
    const int rowBlock = blockIdx.y * 128;
    const int colBlock = blockIdx.x * 128;
    const int head = (H == 2) ? blockIdx.x : 0;

    const int lrow = tid >> 1;            // 0..127
    const int c0   = (tid & 1) * 2;       // chunk16 index 0 or 2

    int gr0 = rowBlock + lrow; if (gr0 >= M) gr0 = M - 1;
    const int gn = colBlock + lrow;
    const __nv_bfloat16* aHiP = Ahi + (size_t)gr0 * 256 + c0 * 8;
    const __nv_bfloat16* aLoP = Alo + (size_t)gr0 * 256 + c0 * 8;
    const __nv_bfloat16* bHiP = Bext + (size_t)gn * 512 + c0 * 8;
    const __nv_bfloat16* bLoP = Bext + (size_t)gn * 512 + 256 + c0 * 8;
    const uint32_t w0 = SWZ(lrow, c0);
    const uint32_t w1 = SWZ(lrow, c0 + 1);

    float c[4][4][4];
#pragma unroll
    for (int i = 0; i < 4; i++)
#pragma unroll
        for (int j = 0; j < 4; j++)
#pragma unroll
            for (int q = 0; q < 4; q++) c[i][j][q] = 0.f;

    auto load_chunk = [&](int cidx) {
        const uint32_t base = sb + (cidx % NSTAGE) * STAGE_B;
        const int kin = cidx * BK;
        CP_ASYNC16(base + 0 * TILE_B + w0, aHiP + kin);
        CP_ASYNC16(base + 0 * TILE_B + w1, aHiP + kin + 8);
        CP_ASYNC16(base + 1 * TILE_B + w0, aLoP + kin);
        CP_ASYNC16(base + 1 * TILE_B + w1, aLoP + kin + 8);
        CP_ASYNC16(base + 2 * TILE_B + w0, bHiP + kin);
        CP_ASYNC16(base + 2 * TILE_B + w1, bHiP + kin + 8);
        CP_ASYNC16(base + 3 * TILE_B + w0, bLoP + kin);
        CP_ASYNC16(base + 3 * TILE_B + w1, bLoP + kin + 8);
    };

    load_chunk(0); CP_COMMIT();
    load_chunk(1); CP_COMMIT();

    for (int cidx = 0; cidx < NCHUNK; cidx++) {
        if (cidx + 1 < NCHUNK) { CP_WAIT1(); } else { CP_WAIT0(); }
        __syncthreads();
        if (cidx + 2 < NCHUNK) { load_chunk(cidx + 2); CP_COMMIT(); }

        const uint32_t stage = sb + (cidx % NSTAGE) * STAGE_B;
        const uint32_t tAhi = stage + 0 * TILE_B;
        const uint32_t tAlo = stage + 1 * TILE_B;
        const uint32_t tBhi = stage + 2 * TILE_B;
        const uint32_t tBlo = stage + 3 * TILE_B;

#pragma unroll
        for (int k16 = 0; k16 < 2; k16++) {
            const int k0 = k16 * 16;

            uint32_t bhi[8], blo[8];
#pragma unroll
            for (int np = 0; np < 2; np++) {
                const int n0 = warpN * 32 + np * 16;
                const int mat = lane >> 3;
                const int row = n0 + ((mat >> 1) << 3) + (lane & 7);
                const int col = k0 + ((mat & 1) << 3);
                const uint32_t off = SWZ(row, col >> 3);
                LDMATRIX_X4(bhi[np*4+0], bhi[np*4+1], bhi[np*4+2], bhi[np*4+3], tBhi + off);
                LDMATRIX_X4(blo[np*4+0], blo[np*4+1], blo[np*4+2], blo[np*4+3], tBlo + off);
            }
            uint32_t ahi[4][4], alo[4][4];
#pragma unroll
            for (int mt = 0; mt < 4; mt++) {
                const int m0 = warpM * 64 + mt * 16;
                const int row = m0 + (lane & 15);
                const int col = k0 + ((lane >> 4) << 3);
                const uint32_t off = SWZ(row, col >> 3);
                LDMATRIX_X4(ahi[mt][0], ahi[mt][1], ahi[mt][2], ahi[mt][3], tAhi + off);
                LDMATRIX_X4(alo[mt][0], alo[mt][1], alo[mt][2], alo[mt][3], tAlo + off);
            }
#pragma unroll
            for (int mt = 0; mt < 4; mt++) {
#pragma unroll
                for (int nt = 0; nt < 4; nt++) {
                    MMA_BF16(c[mt][nt][0], c[mt][nt][1], c[mt][nt][2], c[mt][nt][3],
                             ahi[mt][0], ahi[mt][1], ahi[mt][2], ahi[mt][3],
                             bhi[nt*2], bhi[nt*2+1]);
                    MMA_BF16(c[mt][nt][0], c[mt][nt][1], c[mt][nt][2], c[mt][nt][3],
                             alo[mt][0], alo[mt][1], alo[mt][2], alo[mt][3],
                             bhi[nt*2], bhi[nt*2+1]);
                    MMA_BF16(c[mt][nt][0], c[mt][nt][1], c[mt][nt][2], c[mt][nt][3],
                             ahi[mt][0], ahi[mt][1], ahi[mt][2], ahi[mt][3],
                             blo[nt*2], blo[nt*2+1]);
                }
            }
        }
    }

    // ---- fused alpha partials (fp32 h) ----
    float ps[4][2] = {{0.f,0.f},{0.f,0.f},{0.f,0.f},{0.f,0.f}};
    float pd[4][2] = {{0.f,0.f},{0.f,0.f},{0.f,0.f},{0.f,0.f}};
    {
        const float* avs = a_s + head * 128;
        const float* avd = a_d + head * 128;
#pragma unroll
        for (int nt = 0; nt < 4; nt++) {
            int lc = warpN * 32 + nt * 8 + 2 * (lane & 3);
            float s0 = avs[lc], s1 = avs[lc + 1];
            float d0 = avd[lc], d1 = avd[lc + 1];
#pragma unroll
            for (int mt = 0; mt < 4; mt++) {
                ps[mt][0] += c[mt][nt][0] * s0 + c[mt][nt][1] * s1;
                ps[mt][1] += c[mt][nt][2] * s0 + c[mt][nt][3] * s1;
                pd[mt][0] += c[mt][nt][0] * d0 + c[mt][nt][1] * d1;
                pd[mt][1] += c[mt][nt][2] * d0 + c[mt][nt][3] * d1;
            }
        }
#pragma unroll
        for (int mt = 0; mt < 4; mt++)
#pragma unroll
            for (int r = 0; r < 2; r++) {
                ps[mt][r] += __shfl_xor_sync(0xFFFFFFFFu, ps[mt][r], 1);
                ps[mt][r] += __shfl_xor_sync(0xFFFFFFFFu, ps[mt][r], 2);
                pd[mt][r] += __shfl_xor_sync(0xFFFFFFFFu, pd[mt][r], 1);
                pd[mt][r] += __shfl_xor_sync(0xFFFFFFFFu, pd[mt][r], 2);
            }
    }
    __syncthreads();                       // stage smem no longer needed
    float* sred = (float*)smem;            // [2][128][4]
    if ((lane & 3) == 0) {
#pragma unroll
        for (int mt = 0; mt < 4; mt++) {
            int r0 = warpM * 64 + mt * 16 + (lane >> 2);
            sred[(r0)     * 4 + warpN] = ps[mt][0];
            sred[(r0 + 8) * 4 + warpN] = ps[mt][1];
            sred[(128 + r0)     * 4 + warpN] = pd[mt][0];
            sred[(128 + r0 + 8) * 4 + warpN] = pd[mt][1];
        }
    }

    // C stores (global, overlap with smem writes)
#pragma unroll
    for (int mt = 0; mt < 4; mt++) {
        int r0 = rowBlock + warpM * 64 + mt * 16 + (lane >> 2);
#pragma unroll
        for (int nt = 0; nt < 4; nt++) {
            int cg = colBlock + warpN * 32 + nt * 8 + 2 * (lane & 3);
            if (r0 < M)
                *(__half2*)(C + (size_t)r0 * NCOLS + cg) =
                    __floats2half2_rn(c[mt][nt][0], c[mt][nt][1]);
            if (r0 + 8 < M)
                *(__half2*)(C + (size_t)(r0 + 8) * NCOLS + cg) =
                    __floats2half2_rn(c[mt][nt][2], c[mt][nt][3]);
        }
    }
    __syncthreads();
    if (tid < 128) {
        int gr = rowBlock + tid;
        if (gr < M) {
            float ssum = sred[tid * 4] + sred[tid * 4 + 1] + sred[tid * 4 + 2] + sred[tid * 4 + 3];
            float dsum = sred[(128 + tid) * 4] + sred[(128 + tid) * 4 + 1] +
                         sred[(128 + tid) * 4 + 2] + sred[(128 + tid) * 4 + 3];
            out_s[gr * H + head] = ssum;
            out_d[gr * H + head] = dsum;
        }
    }
}

// ---------------------------------------------------------------------------
// Aggregation (no max pass — softmax shift-invariant, scores O(1))
// ---------------------------------------------------------------------------
__device__ __forceinline__ float warp_sum(float v) {
#pragma unroll
    for (int o = 16; o; o >>= 1) v += __shfl_xor_sync(0xFFFFFFFFu, v, o);
    return v;
}
__device__ __forceinline__ float lrelu(float x) { return x > 0.f ? x : NEG_SLOPE * x; }
__device__ __forceinline__ float eluf(float x)  { return x > 0.f ? x : (__expf(x) - 1.f); }

__device__ __forceinline__ void store4_hilo(__nv_bfloat16* hi, __nv_bfloat16* lo,
                                            size_t off, float4 v) {
    __nv_bfloat16 h0 = __float2bfloat16(v.x), h1 = __float2bfloat16(v.y);
    __nv_bfloat16 h2 = __float2bfloat16(v.z), h3 = __float2bfloat16(v.w);
    __nv_bfloat16 l0 = __float2bfloat16(v.x - __bfloat162float(h0));
    __nv_bfloat16 l1 = __float2bfloat16(v.y - __bfloat162float(h1));
    __nv_bfloat16 l2 = __float2bfloat16(v.z - __bfloat162float(h2));
    __nv_bfloat16 l3 = __float2bfloat16(v.w - __bfloat162float(h3));
    __nv_bfloat162 a, b, cc, d;
    a.x = h0; a.y = h1; b.x = h2; b.y = h3;
    cc.x = l0; cc.y = l1; d.x = l2; d.y = l3;
    *(__nv_bfloat162*)(hi + off)     = a;
    *(__nv_bfloat162*)(hi + off + 2) = b;
    *(__nv_bfloat162*)(lo + off)     = cc;
    *(__nv_bfloat162*)(lo + off + 2) = d;
}

// Layer 1: H=2, C=128/head. out1 = elu(agg + b1), stored as bf16 hi/lo for GEMM2.
__global__ __launch_bounds__(256) void k_agg1(const float* __restrict__ b1)
{
    int w = (blockIdx.x * blockDim.x + threadIdx.x) >> 5;
    int lane = threadIdx.x & 31;
    if (w >= NN) return;
    int node = w;
    int beg = g_rowptr[node], end = g_rowptr[node + 1];
    float ad0 = g_ad1[2 * node], ad1v = g_ad1[2 * node + 1];

    float4 acc0 = make_float4(0.f, 0.f, 0.f, 0.f);
    float4 acc1 = make_float4(0.f, 0.f, 0.f, 0.f);
    float d0 = 0.f, d1 = 0.f;
    const uint2* hbase = (const uint2*)g_h1;   // row = 64 uint2 (256 fp16)

    for (int t = beg; t < end; t += 32) {
        int n = end - t; if (n > 32) n = 32;
        int idx = 0; float w0 = 0.f, w1 = 0.f;
        if (lane < n) {
            idx = g_esrc[t + lane];
            float2 as = *(const float2*)&g_as1[2 * idx];
            w0 = __expf(lrelu(as.x + ad0));
            w1 = __expf(lrelu(as.y + ad1v));
        }
        d0 += w0; d1 += w1;
#pragma unroll 4
        for (int j = 0; j < n; j++) {
            int s    = __shfl_sync(0xFFFFFFFFu, idx, j);
            float u0 = __shfl_sync(0xFFFFFFFFu, w0, j);
            float u1 = __shfl_sync(0xFFFFFFFFu, w1, j);
            uint2 ua = hbase[(size_t)s * 64 + lane];
            uint2 ub = hbase[(size_t)s * 64 + 32 + lane];
            float2 a01 = __half22float2(*(__half2*)&ua.x);
            float2 a23 = __half22float2(*(__half2*)&ua.y);
            float2 b01 = __half22float2(*(__half2*)&ub.x);
            float2 b23 = __half22float2(*(__half2*)&ub.y);
            acc0.x += u0 * a01.x; acc0.y += u0 * a01.y; acc0.z += u0 * a23.x; acc0.w += u0 * a23.y;
            acc1.x += u1 * b01.x; acc1.y += u1 * b01.y; acc1.z += u1 * b23.x; acc1.w += u1 * b23.y;
        }
    }
    d0 = warp_sum(d0); d1 = warp_sum(d1);
    float inv0 = 1.f / d0, inv1 = 1.f / d1;
    float4 bb0 = ((const float4*)b1)[lane];
    float4 bb1 = ((const float4*)b1)[32 + lane];
    float4 o0, o1;
    o0.x = eluf(acc0.x * inv0 + bb0.x);
    o0.y = eluf(acc0.y * inv0 + bb0.y);
    o0.z = eluf(acc0.z * inv0 + bb0.z);
    o0.w = eluf(acc0.w * inv0 + bb0.w);
    o1.x = eluf(acc1.x * inv1 + bb1.x);
    o1.y = eluf(acc1.y * inv1 + bb1.y);
    o1.z = eluf(acc1.z * inv1 + bb1.z);
    o1.w = eluf(acc1.w * inv1 + bb1.w);
    store4_hilo(g_a2hi, g_a2lo, (size_t)node * 256 + lane * 4, o0);
    store4_hilo(g_a2hi, g_a2lo, (size_t)node * 256 + 128 + lane * 4, o1);
}

// Layer 2: H=1, C=128. out = agg + b2 -> d_out (fp32).
__global__ __launch_bounds__(256) void k_agg2(const float* __restrict__ b2,
                                              float* __restrict__ out)
{
    int w = (blockIdx.x * blockDim.x + threadIdx.x) >> 5;
    int lane = threadIdx.x & 31;
    if (w >= NN) return;
    int node = w;
    int beg = g_rowptr[node], end = g_rowptr[node + 1];
    float ad = g_ad2[node];

    float4 acc = make_float4(0.f, 0.f, 0.f, 0.f);
    float d = 0.f;
    const uint2* hbase = (const uint2*)g_h2;   // row = 32 uint2 (128 fp16)

    for (int t = beg; t < end; t += 32) {
        int n = end - t; if (n > 32) n = 32;
        int idx = 0; float wv = 0.f;
        if (lane < n) {
            idx = g_esrc[t + lane];
            wv = __expf(lrelu(g_as2[idx] + ad));
        }
        d += wv;
#pragma unroll 4
        for (int j = 0; j < n; j++) {
            int s   = __shfl_sync(0xFFFFFFFFu, idx, j);
            float u = __shfl_sync(0xFFFFFFFFu, wv, j);
            uint2 uv = hbase[(size_t)s * 32 + lane];
            float2 v01 = __half22float2(*(__half2*)&uv.x);
            float2 v23 = __half22float2(*(__half2*)&uv.y);
            acc.x += u * v01.x; acc.y += u * v01.y; acc.z += u * v23.x; acc.w += u * v23.y;
        }
    }
    d = warp_sum(d);
    float inv = 1.f / d;
    float4 bb = ((const float4*)b2)[lane];
    float4 o;
    o.x = acc.x * inv + bb.x;
    o.y = acc.y * inv + bb.y;
    o.z = acc.z * inv + bb.z;
    o.w = acc.w * inv + bb.w;
    ((float4*)out)[(size_t)node * 32 + lane] = o;
}

// ---------------------------------------------------------------------------
// Launch. Fork used only if stream/event creation verifiably succeeded;
// otherwise serial single-stream order (all deps satisfied either way).
// ---------------------------------------------------------------------------
extern "C" void kernel_launch(void* const* d_in, const int* in_sizes, int n_in,
                              void* d_out, int out_size)
{
    const float* x      = (const float*)d_in[0];
    const int*   eidx   = (const int*)d_in[1];
    const float* W1     = (const float*)d_in[2];
    const float* a_src1 = (const float*)d_in[3];
    const float* a_dst1 = (const float*)d_in[4];
    const float* b1     = (const float*)d_in[5];
    const float* W2     = (const float*)d_in[6];
    const float* a_src2 = (const float*)d_in[7];
    const float* a_dst2 = (const float*)d_in[8];
    const float* b2     = (const float*)d_in[9];
    float* out = (float*)d_out;

    const int* e_src = eidx;
    const int* e_dst = eidx + EE;

    __half* p_h1 = nullptr; cudaGetSymbolAddress((void**)&p_h1, g_h1);
    __half* p_h2 = nullptr; cudaGetSymbolAddress((void**)&p_h2, g_h2);
    float* p_as1 = nullptr; cudaGetSymbolAddress((void**)&p_as1, g_as1);
    float* p_ad1 = nullptr; cudaGetSymbolAddress((void**)&p_ad1, g_ad1);
    float* p_as2 = nullptr; cudaGetSymbolAddress((void**)&p_as2, g_as2);
    float* p_ad2 = nullptr; cudaGetSymbolAddress((void**)&p_ad2, g_ad2);
    __nv_bfloat16 *p_xhi, *p_xlo, *p_a2hi, *p_a2lo, *p_B1, *p_B2;
    cudaGetSymbolAddress((void**)&p_xhi,  g_xhi);
    cudaGetSymbolAddress((void**)&p_xlo,  g_xlo);
    cudaGetSymbolAddress((void**)&p_a2hi, g_a2hi);
    cudaGetSymbolAddress((void**)&p_a2lo, g_a2lo);
    cudaGetSymbolAddress((void**)&p_B1,   g_B1);
    cudaGetSymbolAddress((void**)&p_B2,   g_B2);

    constexpr int GSMEM = NSTAGE * STAGE_B;   // 98304 bytes
    static bool init_done = false;
    static bool use_fork = false;
    static cudaStream_t s2 = nullptr;
    static cudaEvent_t evFork = nullptr, evJoin = nullptr;
    if (!init_done) {
        init_done = true;
        cudaFuncSetAttribute(k_gemm3<256>, cudaFuncAttributeMaxDynamicSharedMemorySize, GSMEM);
        cudaFuncSetAttribute(k_gemm3<128>, cudaFuncAttributeMaxDynamicSharedMemorySize, GSMEM);
        bool ok = (cudaStreamCreateWithFlags(&s2, cudaStreamNonBlocking) == cudaSuccess);
        ok = ok && (cudaEventCreateWithFlags(&evFork, cudaEventDisableTiming) == cudaSuccess);
        ok = ok && (cudaEventCreateWithFlags(&evJoin, cudaEventDisableTiming) == cudaSuccess);
        use_fork = ok && (s2 != nullptr) && (evFork != nullptr) && (evJoin != nullptr);
    }

    if (use_fork) {
        k_prep_all<<<PREP_XB + PREP_W1 + PREP_W2, 256>>>(x, W1, W2);

        cudaEventRecord(evFork, 0);
        cudaStreamWaitEvent(s2, evFork, 0);
        k_init_cnt<<<(NN + 255) / 256, 256, 0, s2>>>();
        k_hist<<<(EE + 255) / 256, 256, 0, s2>>>(e_dst);

        // profiled slot: GEMM1 + fused alpha
        {
            dim3 grid(2, GRID_M);
            k_gemm3<256><<<grid, 256, GSMEM>>>(p_xhi, p_xlo, p_B1, p_h1, NN,
                                               a_src1, a_dst1, p_as1, p_ad1);
        }

        k_scan1<<<SCAN_B, 256, 0, s2>>>();
        k_scan2<<<1, 256, 0, s2>>>();
        k_scan3<<<SCAN_B, 256, 0, s2>>>();
        k_scatter<<<(TOT_E + 255) / 256, 256, 0, s2>>>(e_src, e_dst);
        cudaEventRecord(evJoin, s2);
        cudaStreamWaitEvent(0, evJoin, 0);

        k_agg1<<<(NN * 32 + 255) / 256, 256>>>(b1);
        {
            dim3 grid(1, GRID_M);
            k_gemm3<128><<<grid, 256, GSMEM>>>(p_a2hi, p_a2lo, p_B2, p_h2, NN,
                                               a_src2, a_dst2, p_as2, p_ad2);
        }
        k_agg2<<<(NN * 32 + 255) / 256, 256>>>(b2, out);
    } else {
        // Serial fallback: single stream, all deps in order (cheap scan now).
        k_prep_all<<<PREP_XB + PREP_W1 + PREP_W2, 256>>>(x, W1, W2);
        k_init_cnt<<<(NN + 255) / 256, 256>>>();
        k_hist<<<(EE + 255) / 256, 256>>>(e_dst);
        {
            dim3 grid(2, GRID_M);
            k_gemm3<256><<<grid, 256, GSMEM>>>(p_xhi, p_xlo, p_B1, p_h1, NN,
                                               a_src1, a_dst1, p_as1, p_ad1);
        }
        k_scan1<<<SCAN_B, 256>>>();
        k_scan2<<<1, 256>>>();
        k_scan3<<<SCAN_B, 256>>>();
        k_scatter<<<(TOT_E + 255) / 256, 256>>>(e_src, e_dst);
        k_agg1<<<(NN * 32 + 255) / 256, 256>>>(b1);
        {
            dim3 grid(1, GRID_M);
            k_gemm3<128><<<grid, 256, GSMEM>>>(p_a2hi, p_a2lo, p_B2, p_h2, NN,
                                               a_src2, a_dst2, p_as2, p_ad2);
        }
        k_agg2<<<(NN * 32 + 255) / 256, 256>>>(b2, out);
    }
}

// round 12
// speedup vs baseline: 1.4348x; 1.0025x over previous
#include <cuda_runtime.h>
#include <cuda_bf16.h>
#include <cuda_fp16.h>
#include <cstdint>
#include <cstddef>

// Problem constants
#define NN     50000
#define EE     800000
#define TOT_E  (EE + NN)          // edges + self loops = 850000
#define NEG_SLOPE 0.2f
#define GRID_M ((NN + 127) / 128) // 391
#define SCAN_B ((NN + 255) / 256) // 196

// ---------------------------------------------------------------------------
// Portable async-copy / mma helpers (sm_80+; safe for plain compute_100)
// ---------------------------------------------------------------------------
__device__ __forceinline__ uint32_t smem_u32(const void* p) {
    uint32_t a;
    asm("{ .reg .u64 t; cvta.to.shared.u64 t, %1; cvt.u32.u64 %0, t; }" : "=r"(a) : "l"(p));
    return a;
}
#define CP_ASYNC16(dst, src) \
    asm volatile("cp.async.cg.shared.global [%0], [%1], 16;" :: "r"(dst), "l"(src))
#define CP_COMMIT() asm volatile("cp.async.commit_group;" ::: "memory")
#define CP_WAIT1()  asm volatile("cp.async.wait_group 1;" ::: "memory")
#define CP_WAIT0()  asm volatile("cp.async.wait_group 0;" ::: "memory")

#define LDMATRIX_X4(r0, r1, r2, r3, addr) \
    asm volatile("ldmatrix.sync.aligned.m8n8.x4.shared.b16 {%0,%1,%2,%3}, [%4];" \
        : "=r"(r0), "=r"(r1), "=r"(r2), "=r"(r3) : "r"(addr))

#define MMA_BF16(c0, c1, c2, c3, a0, a1, a2, a3, b0, b1) \
    asm volatile("mma.sync.aligned.m16n8k16.row.col.f32.bf16.bf16.f32 " \
        "{%0,%1,%2,%3}, {%4,%5,%6,%7}, {%8,%9}, {%0,%1,%2,%3};" \
        : "+f"(c0), "+f"(c1), "+f"(c2), "+f"(c3) \
        : "r"(a0), "r"(a1), "r"(a2), "r"(a3), "r"(b0), "r"(b1))

// ---------------------------------------------------------------------------
// Scratch (device globals; no cudaMalloc allowed)
// ---------------------------------------------------------------------------
__device__ __align__(16) __half g_h1[(size_t)NN * 256];   // layer1 linear out (fp16)
__device__ __align__(16) __half g_h2[(size_t)NN * 128];   // layer2 linear out (fp16)
__device__ __align__(16) __nv_bfloat16 g_xhi[(size_t)NN * 256];
__device__ __align__(16) __nv_bfloat16 g_xlo[(size_t)NN * 256];
__device__ __align__(16) __nv_bfloat16 g_a2hi[(size_t)NN * 256];  // out1 hi
__device__ __align__(16) __nv_bfloat16 g_a2lo[(size_t)NN * 256];  // out1 lo
__device__ __align__(16) __nv_bfloat16 g_B1[256 * 512];   // W1 ext: [n][k_ext] hi|lo
__device__ __align__(16) __nv_bfloat16 g_B2[128 * 512];   // W2 ext
__device__ float g_as1[NN * 2];
__device__ float g_ad1[NN * 2];
__device__ float g_as2[NN];
__device__ float g_ad2[NN];
__device__ int   g_cnt[NN];
__device__ int   g_cur[NN];
__device__ int   g_rowptr[NN + 1];
__device__ int   g_esrc[TOT_E];
__device__ int   g_bsum[256];
__device__ int   g_boff[256];

// ---------------------------------------------------------------------------
// CSR build: histogram -> hierarchical coalesced scan -> scatter
// ---------------------------------------------------------------------------
__global__ void k_init_cnt() {
    int i = blockIdx.x * blockDim.x + threadIdx.x;
    if (i < NN) g_cnt[i] = 1;
}
__global__ void k_hist(const int* __restrict__ dst) {
    int i = blockIdx.x * blockDim.x + threadIdx.x;
    if (i < EE) atomicAdd(&g_cnt[dst[i]], 1);
}
__global__ void k_scan1() {
    __shared__ int sm[256];
    int i = blockIdx.x * 256 + threadIdx.x;
    sm[threadIdx.x] = (i < NN) ? g_cnt[i] : 0;
    __syncthreads();
    for (int off = 128; off; off >>= 1) {
        if (threadIdx.x < off) sm[threadIdx.x] += sm[threadIdx.x + off];
        __syncthreads();
    }
    if (threadIdx.x == 0) g_bsum[blockIdx.x] = sm[0];
}
__global__ void k_scan2() {
    __shared__ int sm[256];
    int t = threadIdx.x;
    int v = (t < SCAN_B) ? g_bsum[t] : 0;
    sm[t] = v;
    __syncthreads();
    for (int off = 1; off < 256; off <<= 1) {
        int u = (t >= off) ? sm[t - off] : 0;
        __syncthreads();
        sm[t] += u;
        __syncthreads();
    }
    g_boff[t] = sm[t] - v;   // exclusive
}
__global__ void k_scan3() {
    __shared__ int sm[256];
    int t = threadIdx.x;
    int i = blockIdx.x * 256 + t;
    int v = (i < NN) ? g_cnt[i] : 0;
    sm[t] = v;
    __syncthreads();
    for (int off = 1; off < 256; off <<= 1) {
        int u = (t >= off) ? sm[t - off] : 0;
        __syncthreads();
        sm[t] += u;
        __syncthreads();
    }
    if (i < NN) {
        int excl = sm[t] - v + g_boff[blockIdx.x];
        g_rowptr[i] = excl;
        g_cur[i]    = excl;
        if (i == NN - 1) g_rowptr[NN] = excl + v;
    }
}
__global__ void k_scatter(const int* __restrict__ src, const int* __restrict__ dst) {
    int i = blockIdx.x * blockDim.x + threadIdx.x;
    if (i < EE) {
        int p = atomicAdd(&g_cur[dst[i]], 1);
        g_esrc[p] = src[i];
    } else if (i < TOT_E) {
        int n = i - EE;
        int p = atomicAdd(&g_cur[n], 1);
        g_esrc[p] = n;
    }
}

// ---------------------------------------------------------------------------
// Merged prep: x split (blocks 0..12499) | W1 ext | W2 ext
// ---------------------------------------------------------------------------
#define PREP_XB 12500   // NN*64/256
#define PREP_W1 256     // 256*256/256
#define PREP_W2 128     // 256*128/256

__global__ void k_prep_all(const float* __restrict__ x,
                           const float* __restrict__ W1,
                           const float* __restrict__ W2)
{
    int b = blockIdx.x;
    if (b < PREP_XB) {
        size_t i = (size_t)b * 256 + threadIdx.x;   // float4 index
        float4 v = ((const float4*)x)[i];
        __nv_bfloat16 h0 = __float2bfloat16(v.x), h1 = __float2bfloat16(v.y);
        __nv_bfloat16 h2 = __float2bfloat16(v.z), h3 = __float2bfloat16(v.w);
        __nv_bfloat162 a, bb, c, d;
        a.x = h0; a.y = h1; bb.x = h2; bb.y = h3;
        c.x = __float2bfloat16(v.x - __bfloat162float(h0));
        c.y = __float2bfloat16(v.y - __bfloat162float(h1));
        d.x = __float2bfloat16(v.z - __bfloat162float(h2));
        d.y = __float2bfloat16(v.w - __bfloat162float(h3));
        ((__nv_bfloat162*)g_xhi)[i * 2]     = a;
        ((__nv_bfloat162*)g_xhi)[i * 2 + 1] = bb;
        ((__nv_bfloat162*)g_xlo)[i * 2]     = c;
        ((__nv_bfloat162*)g_xlo)[i * 2 + 1] = d;
    } else if (b < PREP_XB + PREP_W1) {
        int i = (b - PREP_XB) * 256 + threadIdx.x;  // over 256*256
        int k = i >> 8, n = i & 255;
        float v = W1[i];
        __nv_bfloat16 h = __float2bfloat16(v);
        g_B1[(size_t)n * 512 + k]       = h;
        g_B1[(size_t)n * 512 + 256 + k] = __float2bfloat16(v - __bfloat162float(h));
    } else {
        int i = (b - PREP_XB - PREP_W1) * 256 + threadIdx.x;  // over 256*128
        int k = i >> 7, n = i & 127;
        float v = W2[i];
        __nv_bfloat16 h = __float2bfloat16(v);
        g_B2[(size_t)n * 512 + k]       = h;
        g_B2[(size_t)n * 512 + 256 + k] = __float2bfloat16(v - __bfloat162float(h));
    }
}

// ---------------------------------------------------------------------------
// bf16x3 mma.sync GEMM + fused alpha epilogue.
// Term-major MMA ordering: 16 independent accumulators between dependent MMAs.
// ---------------------------------------------------------------------------
#define BK     32
#define TILE_B (128 * 64)          // 8192 bytes per tile
#define STAGE_B (4 * TILE_B)       // Ahi, Alo, Bhi, Blo
#define NSTAGE 3
#define NCHUNK 8                   // 256 / BK
#define SWZ(row, chunk) (((row) << 6) + ((((chunk) ^ (((row) >> 1) & 3))) << 4))

template <int NCOLS>
__global__ __launch_bounds__(256, 2) void k_gemm3(const __nv_bfloat16* __restrict__ Ahi,
                                                  const __nv_bfloat16* __restrict__ Alo,
                                                  const __nv_bfloat16* __restrict__ Bext,
                                                  __half* __restrict__ C, int M,
                                                  const float* __restrict__ a_s,
                                                  const float* __restrict__ a_d,
                                                  float* __restrict__ out_s,
                                                  float* __restrict__ out_d)
{
    extern __shared__ __align__(16) char smem[];
    const uint32_t sb = smem_u32(smem);
    constexpr int H = NCOLS / 128;

    const int tid  = threadIdx.x;
    const int wid  = tid >> 5;
    const int lane = tid & 31;
    const int warpM = wid & 1;      // 2 x 64 rows
    const int warpN = wid >> 1;     // 4 x 32 cols
    const int rowBlock = blockIdx.y * 128;
    const int colBlock = blockIdx.x * 128;
    const int head = (H == 2) ? blockIdx.x : 0;

    const int lrow = tid >> 1;            // 0..127
    const int c0   = (tid & 1) * 2;       // chunk16 index 0 or 2

    int gr0 = rowBlock + lrow; if (gr0 >= M) gr0 = M - 1;
    const int gn = colBlock + lrow;
    const __nv_bfloat16* aHiP = Ahi + (size_t)gr0 * 256 + c0 * 8;
    const __nv_bfloat16* aLoP = Alo + (size_t)gr0 * 256 + c0 * 8;
    const __nv_bfloat16* bHiP = Bext + (size_t)gn * 512 + c0 * 8;
    const __nv_bfloat16* bLoP = Bext + (size_t)gn * 512 + 256 + c0 * 8;
    const uint32_t w0 = SWZ(lrow, c0);
    const uint32_t w1 = SWZ(lrow, c0 + 1);

    float c[4][4][4];
#pragma unroll
    for (int i = 0; i < 4; i++)
#pragma unroll
        for (int j = 0; j < 4; j++)
#pragma unroll
            for (int q = 0; q < 4; q++) c[i][j][q] = 0.f;

    auto load_chunk = [&](int cidx) {
        const uint32_t base = sb + (cidx % NSTAGE) * STAGE_B;
        const int kin = cidx * BK;
        CP_ASYNC16(base + 0 * TILE_B + w0, aHiP + kin);
        CP_ASYNC16(base + 0 * TILE_B + w1, aHiP + kin + 8);
        CP_ASYNC16(base + 1 * TILE_B + w0, aLoP + kin);
        CP_ASYNC16(base + 1 * TILE_B + w1, aLoP + kin + 8);
        CP_ASYNC16(base + 2 * TILE_B + w0, bHiP + kin);
        CP_ASYNC16(base + 2 * TILE_B + w1, bHiP + kin + 8);
        CP_ASYNC16(base + 3 * TILE_B + w0, bLoP + kin);
        CP_ASYNC16(base + 3 * TILE_B + w1, bLoP + kin + 8);
    };

    load_chunk(0); CP_COMMIT();
    load_chunk(1); CP_COMMIT();

    for (int cidx = 0; cidx < NCHUNK; cidx++) {
        if (cidx + 1 < NCHUNK) { CP_WAIT1(); } else { CP_WAIT0(); }
        __syncthreads();
        if (cidx + 2 < NCHUNK) { load_chunk(cidx + 2); CP_COMMIT(); }

        const uint32_t stage = sb + (cidx % NSTAGE) * STAGE_B;
        const uint32_t tAhi = stage + 0 * TILE_B;
        const uint32_t tAlo = stage + 1 * TILE_B;
        const uint32_t tBhi = stage + 2 * TILE_B;
        const uint32_t tBlo = stage + 3 * TILE_B;

#pragma unroll
        for (int k16 = 0; k16 < 2; k16++) {
            const int k0 = k16 * 16;

            uint32_t bhi[8], blo[8];
#pragma unroll
            for (int np = 0; np < 2; np++) {
                const int n0 = warpN * 32 + np * 16;
                const int mat = lane >> 3;
                const int row = n0 + ((mat >> 1) << 3) + (lane & 7);
                const int col = k0 + ((mat & 1) << 3);
                const uint32_t off = SWZ(row, col >> 3);
                LDMATRIX_X4(bhi[np*4+0], bhi[np*4+1], bhi[np*4+2], bhi[np*4+3], tBhi + off);
                LDMATRIX_X4(blo[np*4+0], blo[np*4+1], blo[np*4+2], blo[np*4+3], tBlo + off);
            }
            uint32_t ahi[4][4], alo[4][4];
#pragma unroll
            for (int mt = 0; mt < 4; mt++) {
                const int m0 = warpM * 64 + mt * 16;
                const int row = m0 + (lane & 15);
                const int col = k0 + ((lane >> 4) << 3);
                const uint32_t off = SWZ(row, col >> 3);
                LDMATRIX_X4(ahi[mt][0], ahi[mt][1], ahi[mt][2], ahi[mt][3], tAhi + off);
                LDMATRIX_X4(alo[mt][0], alo[mt][1], alo[mt][2], alo[mt][3], tAlo + off);
            }
            // term-major: all 16 hi*hi, then 16 lo*hi, then 16 hi*lo.
            // Per-accumulator order unchanged (hi*hi, lo*hi, hi*lo) => bit-identical.
#pragma unroll
            for (int mt = 0; mt < 4; mt++)
#pragma unroll
                for (int nt = 0; nt < 4; nt++)
                    MMA_BF16(c[mt][nt][0], c[mt][nt][1], c[mt][nt][2], c[mt][nt][3],
                             ahi[mt][0], ahi[mt][1], ahi[mt][2], ahi[mt][3],
                             bhi[nt*2], bhi[nt*2+1]);
#pragma unroll
            for (int mt = 0; mt < 4; mt++)
#pragma unroll
                for (int nt = 0; nt < 4; nt++)
                    MMA_BF16(c[mt][nt][0], c[mt][nt][1], c[mt][nt][2], c[mt][nt][3],
                             alo[mt][0], alo[mt][1], alo[mt][2], alo[mt][3],
                             bhi[nt*2], bhi[nt*2+1]);
#pragma unroll
            for (int mt = 0; mt < 4; mt++)
#pragma unroll
                for (int nt = 0; nt < 4; nt++)
                    MMA_BF16(c[mt][nt][0], c[mt][nt][1], c[mt][nt][2], c[mt][nt][3],
                             ahi[mt][0], ahi[mt][1], ahi[mt][2], ahi[mt][3],
                             blo[nt*2], blo[nt*2+1]);
        }
    }

    // ---- fused alpha partials (fp32 h) ----
    float ps[4][2] = {{0.f,0.f},{0.f,0.f},{0.f,0.f},{0.f,0.f}};
    float pd[4][2] = {{0.f,0.f},{0.f,0.f},{0.f,0.f},{0.f,0.f}};
    {
        const float* avs = a_s + head * 128;
        const float* avd = a_d + head * 128;
#pragma unroll
        for (int nt = 0; nt < 4; nt++) {
            int lc = warpN * 32 + nt * 8 + 2 * (lane & 3);
            float s0 = avs[lc], s1 = avs[lc + 1];
            float d0 = avd[lc], d1 = avd[lc + 1];
#pragma unroll
            for (int mt = 0; mt < 4; mt++) {
                ps[mt][0] += c[mt][nt][0] * s0 + c[mt][nt][1] * s1;
                ps[mt][1] += c[mt][nt][2] * s0 + c[mt][nt][3] * s1;
                pd[mt][0] += c[mt][nt][0] * d0 + c[mt][nt][1] * d1;
                pd[mt][1] += c[mt][nt][2] * d0 + c[mt][nt][3] * d1;
            }
        }
#pragma unroll
        for (int mt = 0; mt < 4; mt++)
#pragma unroll
            for (int r = 0; r < 2; r++) {
                ps[mt][r] += __shfl_xor_sync(0xFFFFFFFFu, ps[mt][r], 1);
                ps[mt][r] += __shfl_xor_sync(0xFFFFFFFFu, ps[mt][r], 2);
                pd[mt][r] += __shfl_xor_sync(0xFFFFFFFFu, pd[mt][r], 1);
                pd[mt][r] += __shfl_xor_sync(0xFFFFFFFFu, pd[mt][r], 2);
            }
    }
    __syncthreads();                       // stage smem no longer needed
    float* sred = (float*)smem;            // [2][128][4]
    if ((lane & 3) == 0) {
#pragma unroll
        for (int mt = 0; mt < 4; mt++) {
            int r0 = warpM * 64 + mt * 16 + (lane >> 2);
            sred[(r0)     * 4 + warpN] = ps[mt][0];
            sred[(r0 + 8) * 4 + warpN] = ps[mt][1];
            sred[(128 + r0)     * 4 + warpN] = pd[mt][0];
            sred[(128 + r0 + 8) * 4 + warpN] = pd[mt][1];
        }
    }

    // C stores (global, overlap with smem writes)
#pragma unroll
    for (int mt = 0; mt < 4; mt++) {
        int r0 = rowBlock + warpM * 64 + mt * 16 + (lane >> 2);
#pragma unroll
        for (int nt = 0; nt < 4; nt++) {
            int cg = colBlock + warpN * 32 + nt * 8 + 2 * (lane & 3);
            if (r0 < M)
                *(__half2*)(C + (size_t)r0 * NCOLS + cg) =
                    __floats2half2_rn(c[mt][nt][0], c[mt][nt][1]);
            if (r0 + 8 < M)
                *(__half2*)(C + (size_t)(r0 + 8) * NCOLS + cg) =
                    __floats2half2_rn(c[mt][nt][2], c[mt][nt][3]);
        }
    }
    __syncthreads();
    if (tid < 128) {
        int gr = rowBlock + tid;
        if (gr < M) {
            float ssum = sred[tid * 4] + sred[tid * 4 + 1] + sred[tid * 4 + 2] + sred[tid * 4 + 3];
            float dsum = sred[(128 + tid) * 4] + sred[(128 + tid) * 4 + 1] +
                         sred[(128 + tid) * 4 + 2] + sred[(128 + tid) * 4 + 3];
            out_s[gr * H + head] = ssum;
            out_d[gr * H + head] = dsum;
        }
    }
}

// ---------------------------------------------------------------------------
// Aggregation (no max pass — softmax shift-invariant, scores O(1))
// ---------------------------------------------------------------------------
__device__ __forceinline__ float warp_sum(float v) {
#pragma unroll
    for (int o = 16; o; o >>= 1) v += __shfl_xor_sync(0xFFFFFFFFu, v, o);
    return v;
}
__device__ __forceinline__ float lrelu(float x) { return x > 0.f ? x : NEG_SLOPE * x; }
__device__ __forceinline__ float eluf(float x)  { return x > 0.f ? x : (__expf(x) - 1.f); }

__device__ __forceinline__ void store4_hilo(__nv_bfloat16* hi, __nv_bfloat16* lo,
                                            size_t off, float4 v) {
    __nv_bfloat16 h0 = __float2bfloat16(v.x), h1 = __float2bfloat16(v.y);
    __nv_bfloat16 h2 = __float2bfloat16(v.z), h3 = __float2bfloat16(v.w);
    __nv_bfloat16 l0 = __float2bfloat16(v.x - __bfloat162float(h0));
    __nv_bfloat16 l1 = __float2bfloat16(v.y - __bfloat162float(h1));
    __nv_bfloat16 l2 = __float2bfloat16(v.z - __bfloat162float(h2));
    __nv_bfloat16 l3 = __float2bfloat16(v.w - __bfloat162float(h3));
    __nv_bfloat162 a, b, cc, d;
    a.x = h0; a.y = h1; b.x = h2; b.y = h3;
    cc.x = l0; cc.y = l1; d.x = l2; d.y = l3;
    *(__nv_bfloat162*)(hi + off)     = a;
    *(__nv_bfloat162*)(hi + off + 2) = b;
    *(__nv_bfloat162*)(lo + off)     = cc;
    *(__nv_bfloat162*)(lo + off + 2) = d;
}

// Layer 1: H=2, C=128/head. out1 = elu(agg + b1), stored as bf16 hi/lo for GEMM2.
__global__ __launch_bounds__(256) void k_agg1(const float* __restrict__ b1)
{
    int w = (blockIdx.x * blockDim.x + threadIdx.x) >> 5;
    int lane = threadIdx.x & 31;
    if (w >= NN) return;
    int node = w;
    int beg = g_rowptr[node], end = g_rowptr[node + 1];
    float ad0 = g_ad1[2 * node], ad1v = g_ad1[2 * node + 1];

    float4 acc0 = make_float4(0.f, 0.f, 0.f, 0.f);
    float4 acc1 = make_float4(0.f, 0.f, 0.f, 0.f);
    float d0 = 0.f, d1 = 0.f;
    const uint2* hbase = (const uint2*)g_h1;   // row = 64 uint2 (256 fp16)

    for (int t = beg; t < end; t += 32) {
        int n = end - t; if (n > 32) n = 32;
        int idx = 0; float w0 = 0.f, w1 = 0.f;
        if (lane < n) {
            idx = g_esrc[t + lane];
            float2 as = *(const float2*)&g_as1[2 * idx];
            w0 = __expf(lrelu(as.x + ad0));
            w1 = __expf(lrelu(as.y + ad1v));
        }
        d0 += w0; d1 += w1;
#pragma unroll 4
        for (int j = 0; j < n; j++) {
            int s    = __shfl_sync(0xFFFFFFFFu, idx, j);
            float u0 = __shfl_sync(0xFFFFFFFFu, w0, j);
            float u1 = __shfl_sync(0xFFFFFFFFu, w1, j);
            uint2 ua = hbase[(size_t)s * 64 + lane];
            uint2 ub = hbase[(size_t)s * 64 + 32 + lane];
            float2 a01 = __half22float2(*(__half2*)&ua.x);
            float2 a23 = __half22float2(*(__half2*)&ua.y);
            float2 b01 = __half22float2(*(__half2*)&ub.x);
            float2 b23 = __half22float2(*(__half2*)&ub.y);
            acc0.x += u0 * a01.x; acc0.y += u0 * a01.y; acc0.z += u0 * a23.x; acc0.w += u0 * a23.y;
            acc1.x += u1 * b01.x; acc1.y += u1 * b01.y; acc1.z += u1 * b23.x; acc1.w += u1 * b23.y;
        }
    }
    d0 = warp_sum(d0); d1 = warp_sum(d1);
    float inv0 = 1.f / d0, inv1 = 1.f / d1;
    float4 bb0 = ((const float4*)b1)[lane];
    float4 bb1 = ((const float4*)b1)[32 + lane];
    float4 o0, o1;
    o0.x = eluf(acc0.x * inv0 + bb0.x);
    o0.y = eluf(acc0.y * inv0 + bb0.y);
    o0.z = eluf(acc0.z * inv0 + bb0.z);
    o0.w = eluf(acc0.w * inv0 + bb0.w);
    o1.x = eluf(acc1.x * inv1 + bb1.x);
    o1.y = eluf(acc1.y * inv1 + bb1.y);
    o1.z = eluf(acc1.z * inv1 + bb1.z);
    o1.w = eluf(acc1.w * inv1 + bb1.w);
    store4_hilo(g_a2hi, g_a2lo, (size_t)node * 256 + lane * 4, o0);
    store4_hilo(g_a2hi, g_a2lo, (size_t)node * 256 + 128 + lane * 4, o1);
}

// Layer 2: H=1, C=128. out = agg + b2 -> d_out (fp32).
__global__ __launch_bounds__(256) void k_agg2(const float* __restrict__ b2,
                                              float* __restrict__ out)
{
    int w = (blockIdx.x * blockDim.x + threadIdx.x) >> 5;
    int lane = threadIdx.x & 31;
    if (w >= NN) return;
    int node = w;
    int beg = g_rowptr[node], end = g_rowptr[node + 1];
    float ad = g_ad2[node];

    float4 acc = make_float4(0.f, 0.f, 0.f, 0.f);
    float d = 0.f;
    const uint2* hbase = (const uint2*)g_h2;   // row = 32 uint2 (128 fp16)

    for (int t = beg; t < end; t += 32) {
        int n = end - t; if (n > 32) n = 32;
        int idx = 0; float wv = 0.f;
        if (lane < n) {
            idx = g_esrc[t + lane];
            wv = __expf(lrelu(g_as2[idx] + ad));
        }
        d += wv;
#pragma unroll 4
        for (int j = 0; j < n; j++) {
            int s   = __shfl_sync(0xFFFFFFFFu, idx, j);
            float u = __shfl_sync(0xFFFFFFFFu, wv, j);
            uint2 uv = hbase[(size_t)s * 32 + lane];
            float2 v01 = __half22float2(*(__half2*)&uv.x);
            float2 v23 = __half22float2(*(__half2*)&uv.y);
            acc.x += u * v01.x; acc.y += u * v01.y; acc.z += u * v23.x; acc.w += u * v23.y;
        }
    }
    d = warp_sum(d);
    float inv = 1.f / d;
    float4 bb = ((const float4*)b2)[lane];
    float4 o;
    o.x = acc.x * inv + bb.x;
    o.y = acc.y * inv + bb.y;
    o.z = acc.z * inv + bb.z;
    o.w = acc.w * inv + bb.w;
    ((float4*)out)[(size_t)node * 32 + lane] = o;
}

// ---------------------------------------------------------------------------
// Launch. Fork used only if stream/event creation verifiably succeeded;
// otherwise serial single-stream order (all deps satisfied either way).
// ---------------------------------------------------------------------------
extern "C" void kernel_launch(void* const* d_in, const int* in_sizes, int n_in,
                              void* d_out, int out_size)
{
    const float* x      = (const float*)d_in[0];
    const int*   eidx   = (const int*)d_in[1];
    const float* W1     = (const float*)d_in[2];
    const float* a_src1 = (const float*)d_in[3];
    const float* a_dst1 = (const float*)d_in[4];
    const float* b1     = (const float*)d_in[5];
    const float* W2     = (const float*)d_in[6];
    const float* a_src2 = (const float*)d_in[7];
    const float* a_dst2 = (const float*)d_in[8];
    const float* b2     = (const float*)d_in[9];
    float* out = (float*)d_out;

    const int* e_src = eidx;
    const int* e_dst = eidx + EE;

    __half* p_h1 = nullptr; cudaGetSymbolAddress((void**)&p_h1, g_h1);
    __half* p_h2 = nullptr; cudaGetSymbolAddress((void**)&p_h2, g_h2);
    float* p_as1 = nullptr; cudaGetSymbolAddress((void**)&p_as1, g_as1);
    float* p_ad1 = nullptr; cudaGetSymbolAddress((void**)&p_ad1, g_ad1);
    float* p_as2 = nullptr; cudaGetSymbolAddress((void**)&p_as2, g_as2);
    float* p_ad2 = nullptr; cudaGetSymbolAddress((void**)&p_ad2, g_ad2);
    __nv_bfloat16 *p_xhi, *p_xlo, *p_a2hi, *p_a2lo, *p_B1, *p_B2;
    cudaGetSymbolAddress((void**)&p_xhi,  g_xhi);
    cudaGetSymbolAddress((void**)&p_xlo,  g_xlo);
    cudaGetSymbolAddress((void**)&p_a2hi, g_a2hi);
    cudaGetSymbolAddress((void**)&p_a2lo, g_a2lo);
    cudaGetSymbolAddress((void**)&p_B1,   g_B1);
    cudaGetSymbolAddress((void**)&p_B2,   g_B2);

    constexpr int GSMEM = NSTAGE * STAGE_B;   // 98304 bytes
    static bool init_done = false;
    static bool use_fork = false;
    static cudaStream_t s2 = nullptr;
    static cudaEvent_t evFork = nullptr, evJoin = nullptr;
    if (!init_done) {
        init_done = true;
        cudaFuncSetAttribute(k_gemm3<256>, cudaFuncAttributeMaxDynamicSharedMemorySize, GSMEM);
        cudaFuncSetAttribute(k_gemm3<128>, cudaFuncAttributeMaxDynamicSharedMemorySize, GSMEM);
        bool ok = (cudaStreamCreateWithFlags(&s2, cudaStreamNonBlocking) == cudaSuccess);
        ok = ok && (cudaEventCreateWithFlags(&evFork, cudaEventDisableTiming) == cudaSuccess);
        ok = ok && (cudaEventCreateWithFlags(&evJoin, cudaEventDisableTiming) == cudaSuccess);
        use_fork = ok && (s2 != nullptr) && (evFork != nullptr) && (evJoin != nullptr);
    }

    if (use_fork) {
        k_prep_all<<<PREP_XB + PREP_W1 + PREP_W2, 256>>>(x, W1, W2);

        cudaEventRecord(evFork, 0);
        cudaStreamWaitEvent(s2, evFork, 0);
        k_init_cnt<<<(NN + 255) / 256, 256, 0, s2>>>();
        k_hist<<<(EE + 255) / 256, 256, 0, s2>>>(e_dst);

        // profiled slot: GEMM1 + fused alpha
        {
            dim3 grid(2, GRID_M);
            k_gemm3<256><<<grid, 256, GSMEM>>>(p_xhi, p_xlo, p_B1, p_h1, NN,
                                               a_src1, a_dst1, p_as1, p_ad1);
        }

        k_scan1<<<SCAN_B, 256, 0, s2>>>();
        k_scan2<<<1, 256, 0, s2>>>();
        k_scan3<<<SCAN_B, 256, 0, s2>>>();
        k_scatter<<<(TOT_E + 255) / 256, 256, 0, s2>>>(e_src, e_dst);
        cudaEventRecord(evJoin, s2);
        cudaStreamWaitEvent(0, evJoin, 0);

        k_agg1<<<(NN * 32 + 255) / 256, 256>>>(b1);
        {
            dim3 grid(1, GRID_M);
            k_gemm3<128><<<grid, 256, GSMEM>>>(p_a2hi, p_a2lo, p_B2, p_h2, NN,
                                               a_src2, a_dst2, p_as2, p_ad2);
        }
        k_agg2<<<(NN * 32 + 255) / 256, 256>>>(b2, out);
    } else {
        // Serial fallback: single stream, all deps in order.
        k_prep_all<<<PREP_XB + PREP_W1 + PREP_W2, 256>>>(x, W1, W2);
        k_init_cnt<<<(NN + 255) / 256, 256>>>();
        k_hist<<<(EE + 255) / 256, 256>>>(e_dst);
        {
            dim3 grid(2, GRID_M);
            k_gemm3<256><<<grid, 256, GSMEM>>>(p_xhi, p_xlo, p_B1, p_h1, NN,
                                               a_src1, a_dst1, p_as1, p_ad1);
        }
        k_scan1<<<SCAN_B, 256>>>();
        k_scan2<<<1, 256>>>();
        k_scan3<<<SCAN_B, 256>>>();
        k_scatter<<<(TOT_E + 255) / 256, 256>>>(e_src, e_dst);
        k_agg1<<<(NN * 32 + 255) / 256, 256>>>(b1);
        {
            dim3 grid(1, GRID_M);
            k_gemm3<128><<<grid, 256, GSMEM>>>(p_a2hi, p_a2lo, p_B2, p_h2, NN,
                                               a_src2, a_dst2, p_as2, p_ad2);
        }
        k_agg2<<<(NN * 32 + 255) / 256, 256>>>(b2, out);
    }
}